// round 13
// baseline (speedup 1.0000x reference)
#include <cuda_runtime.h>

#define BB   4
#define NR   2
#define NREF 4
#define HH   320
#define WW   320
#define NPIX (HH*WW)

// Quad image: entry (ey,ex), ey,ex in [0,322]; top-left texel (ey-2, ex-2);
// entry = { t(y0,x0), t(y0,x0+1), t(y0+1,x0), t(y0+1,x0+1) }, zero outside image.
#define QDIM  (WW+3)            // 323
#define IMGQ  (QDIM*QDIM)

// Repack tiling: 64x32 entries per block, 65x33 unique-texel halo in smem.
#define TILE_X 64
#define TILE_Y 32
#define HALO_X (TILE_X+1)       // 65
#define HALO_Y (TILE_Y+1)       // 33
#define RB_X   6                // ceil(323/64)
#define RB_Y   11               // ceil(323/32)
#define RPB    (RB_X*RB_Y)      // 66 repack blocks per ref
#define R_TOT  (RPB*BB*NREF)    // 1056 repack blocks
#define D_TOT  (BB*NR*400)      // 3200 render blocks (10 x 40 tiles of 32x8)

__device__ float g_A[BB*NR][12];    // invR@invK ; -invR@t
__device__ float g_P[BB*NREF][12];  // Kref@Rref ; Kref@tref
__device__ uint4 g_q[BB*NREF*IMGQ]; // 26.7 MB quad image
__device__ int   g_done[BB*NREF];   // per-ref repack completion counters

__device__ __forceinline__ void inv3x3(const float m[9], float o[9]) {
    float a=m[0],b=m[1],c=m[2],d=m[3],e=m[4],f=m[5],g=m[6],h=m[7],i=m[8];
    float c00 =  (e*i - f*h);
    float c01 = -(d*i - f*g);
    float c02 =  (d*h - e*g);
    float det = a*c00 + b*c01 + c*c02;
    float id  = 1.0f/det;
    o[0]=c00*id;        o[1]=(c*h-b*i)*id;  o[2]=(b*f-c*e)*id;
    o[3]=c01*id;        o[4]=(a*i-c*g)*id;  o[5]=(c*d-a*f)*id;
    o[6]=c02*id;        o[7]=(b*g-a*h)*id;  o[8]=(a*e-b*d)*id;
}

__device__ __forceinline__ void precompute_mats(int t,
                                                const float* __restrict__ camK,
                                                const float* __restrict__ camW,
                                                const float* __restrict__ camKref,
                                                const float* __restrict__ camWref) {
    if (t < BB*NR) {
        float K[9], R[9], tv[3], invK[9], invR[9];
        #pragma unroll
        for (int i=0;i<9;i++) K[i]=camK[t*9+i];
        #pragma unroll
        for (int r=0;r<3;r++){
            #pragma unroll
            for(int c=0;c<3;c++) R[r*3+c]=camW[t*12+r*4+c];
            tv[r]=camW[t*12+r*4+3];
        }
        inv3x3(K, invK);
        inv3x3(R, invR);
        #pragma unroll
        for (int r=0;r<3;r++) {
            #pragma unroll
            for (int c=0;c<3;c++) {
                float s=0.f;
                #pragma unroll
                for (int k=0;k<3;k++) s += invR[r*3+k]*invK[k*3+c];
                g_A[t][r*3+c]=s;
            }
            float s=0.f;
            #pragma unroll
            for (int k=0;k<3;k++) s += invR[r*3+k]*tv[k];
            g_A[t][9+r] = -s;
        }
    }
    if (t < BB*NREF) {
        float K[9], R[9], tv[3];
        #pragma unroll
        for (int i=0;i<9;i++) K[i]=camKref[t*9+i];
        #pragma unroll
        for (int r=0;r<3;r++){
            #pragma unroll
            for(int c=0;c<3;c++) R[r*3+c]=camWref[t*12+r*4+c];
            tv[r]=camWref[t*12+r*4+3];
        }
        #pragma unroll
        for (int r=0;r<3;r++) {
            #pragma unroll
            for (int c=0;c<3;c++) {
                float s=0.f;
                #pragma unroll
                for (int k=0;k<3;k++) s += K[r*3+k]*R[k*3+c];
                g_P[t][r*3+c]=s;
            }
            float s=0.f;
            #pragma unroll
            for (int k=0;k<3;k++) s += K[r*3+k]*tv[k];
            g_P[t][9+r]=s;
        }
    }
}

__device__ __forceinline__ unsigned pack_tex(const float* __restrict__ src, int pix) {
    float r = src[pix];
    float g = src[pix + NPIX];
    float b = src[pix + 2*NPIX];
    unsigned ri = __float2uint_rn(r * 2047.f);
    unsigned gi = __float2uint_rn(g * 2047.f);
    unsigned bi = __float2uint_rn(b * 1023.f);
    return ri | (gi << 11) | (bi << 22);
}

// Mantissa-OR decode: f = 1 + field * 2^-k, no I2F.
__device__ __forceinline__ void dec_acc(unsigned t, float w,
                                        float& a0, float& a1, float& a2) {
    float fr = __uint_as_float(((t << 12) & 0x7FF000u) | 0x3F800000u);
    float fg = __uint_as_float(((t << 1)  & 0x7FF000u) | 0x3F800000u);
    float fb = __uint_as_float(((t >> 9)  & 0x7FE000u) | 0x3F800000u);
    a0 = fmaf(w, fr, a0);
    a1 = fmaf(w, fg, a1);
    a2 = fmaf(w, fb, a2);
}

// Fused producer-consumer kernel. 1D grid, bids [0, R_TOT) = repack
// (ref-major, never waits), bids [R_TOT, R_TOT+D_TOT) = render (cam-major,
// spins on its batch's ref counters). Wave-1 schedules all repack first;
// render CTAs fill in as repack retires -> repack BW hidden under render.
__global__ __launch_bounds__(256, 8)
void fused_kernel(const float* __restrict__ image_ref,
                  const float* __restrict__ camK,
                  const float* __restrict__ camW,
                  const float* __restrict__ camKref,
                  const float* __restrict__ camWref,
                  const float* __restrict__ depth,
                  const float* __restrict__ background,
                  float* __restrict__ out) {
    __shared__ unsigned s_t[HALO_Y][HALO_X];
    int bid = blockIdx.x;
    int tid = threadIdx.x;

    if (bid < R_TOT) {
        // ---------------- repack block ----------------
        if (bid == 0 && tid < 32)
            precompute_mats(tid, camK, camW, camKref, camWref);

        int rf  = bid / RPB;
        int t6  = bid - rf*RPB;
        int ex0 = (t6 % RB_X) * TILE_X;
        int ey0 = (t6 / RB_X) * TILE_Y;
        const float* src = image_ref + (size_t)rf*3*NPIX;

        // pack unique texel halo once
        for (int idx = tid; idx < HALO_Y*HALO_X; idx += 256) {
            int ly = idx / HALO_X;
            int lx = idx - ly*HALO_X;
            int ty = ey0 - 2 + ly;
            int tx = ex0 - 2 + lx;
            unsigned v = 0u;
            if ((unsigned)ty < HH && (unsigned)tx < WW)
                v = pack_tex(src, ty*WW + tx);
            s_t[ly][lx] = v;
        }
        __syncthreads();

        // assemble quad entries, 8 per thread, STG.128 each
        uint4* dst = g_q + (size_t)rf*IMGQ;
        #pragma unroll
        for (int k = 0; k < 8; k++) {
            int e   = k*256 + tid;
            int lex = e & (TILE_X-1);
            int ley = e >> 6;
            int ex  = ex0 + lex;
            int ey  = ey0 + ley;
            if (ex < QDIM && ey < QDIM) {
                uint4 v;
                v.x = s_t[ley][lex];
                v.y = s_t[ley][lex+1];
                v.z = s_t[ley+1][lex];
                v.w = s_t[ley+1][lex+1];
                dst[ey*QDIM + ex] = v;
            }
        }

        __threadfence();          // make this thread's stores device-visible
        __syncthreads();          // all threads fenced
        if (tid == 0)
            atomicAdd(&g_done[rf], 1);
        return;
    }

    // ---------------- render block ----------------
    int rid = bid - R_TOT;
    int cam = rid / 400;               // cam-major: batch pipelining
    int rem = rid - cam*400;
    int by  = rem / 10;
    int bx  = rem - by*10;
    int b   = cam >> 1;                // NR == 2

    int x = bx*32 + (tid & 31);
    int y = by*8  + (tid >> 5);
    int pix = y*WW + x;
    float d = depth[cam*NPIX + pix];   // independent load before the wait
    size_t obase = (size_t)cam*3*NPIX + pix;
    bool m = d > 0.f;

    // wait for this batch's refs (+ref 0, which gates the camera matrices)
    if (tid == 0) {
        #pragma unroll
        for (int i = 0; i < NREF; i++)
            while (atomicAdd(&g_done[b*NREF + i], 0) < RPB) __nanosleep(64);
        while (atomicAdd(&g_done[0], 0) < RPB) __nanosleep(64);
        __threadfence();
    }
    __syncthreads();

    const float* Ac = g_A[cam];
    float fx = (float)x, fy = (float)y;
    float hx = Ac[0]*fx + Ac[1]*fy + Ac[2];
    float hy = Ac[3]*fx + Ac[4]*fy + Ac[5];
    float hz = Ac[6]*fx + Ac[7]*fy + Ac[8];
    float px = -d*hx + Ac[9];
    float py = -d*hy + Ac[10];
    float pz = -d*hz + Ac[11];

    // Phase 1: all 4 sites
    int   idxA[NREF];
    float wxA[NREF], wyA[NREF];
    #pragma unroll
    for (int r=0; r<NREF; r++) {
        const float* P = g_P[b*NREF + r];
        float qx = P[0]*px + P[1]*py + P[2]*pz + P[9];
        float qy = P[3]*px + P[4]*py + P[5]*pz + P[10];
        float qz = P[6]*px + P[7]*py + P[8]*pz + P[11];
        float inv = __fdividef(1.f, qz);
        float u = qx*inv;
        float v = qy*inv;
        float x0f = floorf(u), y0f = floorf(v);
        wxA[r] = u - x0f;
        wyA[r] = v - y0f;
        int ex = min(max(__float2int_rz(x0f) + 2, 0), QDIM-1);
        int ey = min(max(__float2int_rz(y0f) + 2, 0), QDIM-1);
        idxA[r] = m ? (ey*QDIM + ex) : 0;   // masked: zero entry broadcast
    }

    // Phase 2: 4 LDG.128 back-to-back
    uint4 T[NREF];
    #pragma unroll
    for (int r=0; r<NREF; r++)
        T[r] = __ldg(g_q + (size_t)(b*NREF + r)*IMGQ + idxA[r]);

    // Phase 3: decode + accumulate
    float a0=0.f, a1=0.f, a2=0.f;
    #pragma unroll
    for (int r=0; r<NREF; r++) {
        float wx = wxA[r], wy = wyA[r];
        float wxl = 1.f - wx, wyt = 1.f - wy;
        float w00 = wxl*wyt, w01 = wx*wyt;
        float w10 = wxl*wy,  w11 = wx*wy;   // sums to 1 -> bias = NREF
        dec_acc(T[r].x, w00, a0, a1, a2);
        dec_acc(T[r].y, w01, a0, a1, a2);
        dec_acc(T[r].z, w10, a0, a1, a2);
        dec_acc(T[r].w, w11, a0, a1, a2);
    }

    const float sRG = 0.25f * 2048.f / 2047.f;
    const float sB  = 0.25f * 1024.f / 1023.f;
    const float bRG = -4.f * sRG;
    const float bB  = -4.f * sB;

    float o0, o1, o2;
    if (m) {
        o0 = fmaf(a0, sRG, bRG);
        o1 = fmaf(a1, sRG, bRG);
        o2 = fmaf(a2, sB,  bB );
    } else {
        o0 = background[obase];
        o1 = background[obase + NPIX];
        o2 = background[obase + 2*NPIX];
    }

    out[obase]          = o0;
    out[obase + NPIX]   = o1;
    out[obase + 2*NPIX] = o2;
}

extern "C" void kernel_launch(void* const* d_in, const int* in_sizes, int n_in,
                              void* d_out, int out_size) {
    // metadata order: depth, cam_K, cam_W, image_ref, background,
    //                 cube_diagonal, cam_K_ref, cam_W_ref
    const float* depth      = (const float*)d_in[0];
    const float* cam_K      = (const float*)d_in[1];
    const float* cam_W      = (const float*)d_in[2];
    const float* image_ref  = (const float*)d_in[3];
    const float* background = (const float*)d_in[4];
    // d_in[5] = cube_diagonal: algebraically cancels -> unused
    const float* cam_K_ref  = (const float*)d_in[6];
    const float* cam_W_ref  = (const float*)d_in[7];
    float* out = (float*)d_out;

    // reset the per-ref completion counters (graph-replay-safe memset node)
    void* done_ptr = nullptr;
    cudaGetSymbolAddress(&done_ptr, g_done);
    cudaMemsetAsync(done_ptr, 0, sizeof(int)*BB*NREF);

    fused_kernel<<<R_TOT + D_TOT, 256>>>(image_ref, cam_K, cam_W,
                                         cam_K_ref, cam_W_ref,
                                         depth, background, out);
}

// round 14
// speedup vs baseline: 1.2572x; 1.2572x over previous
#include <cuda_runtime.h>

#define BB   4
#define NR   2
#define NREF 4
#define HH   320
#define WW   320
#define NPIX (HH*WW)

// Vertical-pair image: entry (ey, ex), ey,ex in [0, 323].
// Logical texel column x = ex-2, rows y = ey-2 (v.x) and y = ey-1+... :
//   v.x = t(ey-2, ex-2), v.y = t(ey-1, ex-2)   [i.e. t(y, x), t(y+1, x)]
// Zero outside [0,HH) x [0,WW).  A bilinear fetch = entries (ey,ex), (ey,ex+1)
// -> two adjacent 8B loads, same 128B line ~94% of the time.
#define VDIM  (WW+4)            // 324 (cols and rows both padded by 2)
#define IMGV  (VDIM*VDIM)       // 104976 entries per ref image

__device__ float g_A[BB*NR][12];    // invR@invK ; -invR@t
__device__ float g_P[BB*NREF][12];  // Kref@Rref ; Kref@tref

// 16 * 324*324 * 8B = 13.4 MB
__device__ uint2 g_v[BB*NREF*IMGV];

__device__ __forceinline__ void inv3x3(const float m[9], float o[9]) {
    float a=m[0],b=m[1],c=m[2],d=m[3],e=m[4],f=m[5],g=m[6],h=m[7],i=m[8];
    float c00 =  (e*i - f*h);
    float c01 = -(d*i - f*g);
    float c02 =  (d*h - e*g);
    float det = a*c00 + b*c01 + c*c02;
    float id  = 1.0f/det;
    o[0]=c00*id;        o[1]=(c*h-b*i)*id;  o[2]=(b*f-c*e)*id;
    o[3]=c01*id;        o[4]=(a*i-c*g)*id;  o[5]=(c*d-a*f)*id;
    o[6]=c02*id;        o[7]=(b*g-a*h)*id;  o[8]=(a*e-b*d)*id;
}

__device__ __forceinline__ void precompute_mats(int t,
                                                const float* __restrict__ camK,
                                                const float* __restrict__ camW,
                                                const float* __restrict__ camKref,
                                                const float* __restrict__ camWref) {
    if (t < BB*NR) {
        float K[9], R[9], tv[3], invK[9], invR[9];
        #pragma unroll
        for (int i=0;i<9;i++) K[i]=camK[t*9+i];
        #pragma unroll
        for (int r=0;r<3;r++){
            #pragma unroll
            for(int c=0;c<3;c++) R[r*3+c]=camW[t*12+r*4+c];
            tv[r]=camW[t*12+r*4+3];
        }
        inv3x3(K, invK);
        inv3x3(R, invR);
        #pragma unroll
        for (int r=0;r<3;r++) {
            #pragma unroll
            for (int c=0;c<3;c++) {
                float s=0.f;
                #pragma unroll
                for (int k=0;k<3;k++) s += invR[r*3+k]*invK[k*3+c];
                g_A[t][r*3+c]=s;
            }
            float s=0.f;
            #pragma unroll
            for (int k=0;k<3;k++) s += invR[r*3+k]*tv[k];
            g_A[t][9+r] = -s;
        }
    }
    if (t < BB*NREF) {
        float K[9], R[9], tv[3];
        #pragma unroll
        for (int i=0;i<9;i++) K[i]=camKref[t*9+i];
        #pragma unroll
        for (int r=0;r<3;r++){
            #pragma unroll
            for(int c=0;c<3;c++) R[r*3+c]=camWref[t*12+r*4+c];
            tv[r]=camWref[t*12+r*4+3];
        }
        #pragma unroll
        for (int r=0;r<3;r++) {
            #pragma unroll
            for (int c=0;c<3;c++) {
                float s=0.f;
                #pragma unroll
                for (int k=0;k<3;k++) s += K[r*3+k]*R[k*3+c];
                g_P[t][r*3+c]=s;
            }
            float s=0.f;
            #pragma unroll
            for (int k=0;k<3;k++) s += K[r*3+k]*tv[k];
            g_P[t][9+r]=s;
        }
    }
}

__device__ __forceinline__ unsigned pack_tex(const float* __restrict__ src, int pix) {
    float r = src[pix];
    float g = src[pix + NPIX];
    float b = src[pix + 2*NPIX];
    unsigned ri = __float2uint_rn(r * 2047.f);
    unsigned gi = __float2uint_rn(g * 2047.f);
    unsigned bi = __float2uint_rn(b * 1023.f);
    return ri | (gi << 11) | (bi << 22);
}

// Planar float (rf,3,H,W) -> vertical-pair image (R8-style flat repack, proven ~5.3us).
// Block 0 additionally folds the camera matrices.
__global__ __launch_bounds__(256)
void repack_kernel(const float* __restrict__ image_ref,
                   const float* __restrict__ camK,
                   const float* __restrict__ camW,
                   const float* __restrict__ camKref,
                   const float* __restrict__ camWref) {
    if (blockIdx.x == 0 && threadIdx.x < 32)
        precompute_mats(threadIdx.x, camK, camW, camKref, camWref);

    int i = blockIdx.x*256 + threadIdx.x;      // over BB*NREF*IMGV = 256*6561
    int rf  = i / IMGV;
    int rem = i - rf*IMGV;
    int ey  = rem / VDIM;
    int ex  = rem - ey*VDIM;

    int x  = ex - 2;
    int y0 = ey - 2;
    int y1 = ey - 1;

    uint2 v = make_uint2(0u, 0u);
    if ((unsigned)x < WW) {
        const float* src = image_ref + (size_t)rf*3*NPIX;
        if ((unsigned)y0 < HH) v.x = pack_tex(src, y0*WW + x);
        if ((unsigned)y1 < HH) v.y = pack_tex(src, y1*WW + x);
    }
    g_v[i] = v;
}

// Mantissa-OR decode: f = 1 + field * 2^-k, no I2F.
__device__ __forceinline__ void dec_acc(unsigned t, float w,
                                        float& a0, float& a1, float& a2) {
    float fr = __uint_as_float(((t << 12) & 0x7FF000u) | 0x3F800000u); // 1+r*2^-11
    float fg = __uint_as_float(((t << 1)  & 0x7FF000u) | 0x3F800000u); // 1+g*2^-11
    float fb = __uint_as_float(((t >> 9)  & 0x7FE000u) | 0x3F800000u); // 1+b*2^-10
    a0 = fmaf(w, fr, a0);
    a1 = fmaf(w, fg, a1);
    a2 = fmaf(w, fb, a2);
}

// 1 px/thread; branch-free; per ref-sample 2 ADJACENT LDG.64 (same line ~94%).
// All 8 loads staged back-to-back. Masked pixels read entry 0 (zero, broadcast).
__global__ __launch_bounds__(256)
void render_kernel(const float* __restrict__ depth,
                   const float* __restrict__ background,
                   float* __restrict__ out) {
    int x   = blockIdx.x*32 + threadIdx.x;
    int y   = blockIdx.y*8  + threadIdx.y;
    int cam = blockIdx.z;                  // b*NR + nr
    int b   = cam >> 1;                    // NR == 2

    int pix = y*WW + x;
    float d = depth[cam*NPIX + pix];
    size_t obase = (size_t)cam*3*NPIX + pix;
    bool m = d > 0.f;

    const float* Ac = g_A[cam];
    float fx = (float)x, fy = (float)y;
    float hx = Ac[0]*fx + Ac[1]*fy + Ac[2];
    float hy = Ac[3]*fx + Ac[4]*fy + Ac[5];
    float hz = Ac[6]*fx + Ac[7]*fy + Ac[8];
    float px = -d*hx + Ac[9];
    float py = -d*hy + Ac[10];
    float pz = -d*hz + Ac[11];

    // Phase 1: all 4 sites
    int   idxA[NREF];
    float wxA[NREF], wyA[NREF];
    #pragma unroll
    for (int r=0; r<NREF; r++) {
        const float* P = g_P[b*NREF + r];
        float qx = P[0]*px + P[1]*py + P[2]*pz + P[9];
        float qy = P[3]*px + P[4]*py + P[5]*pz + P[10];
        float qz = P[6]*px + P[7]*py + P[8]*pz + P[11];
        float inv = __fdividef(1.f, qz);
        float u = qx*inv;
        float v = qy*inv;
        float x0f = floorf(u), y0f = floorf(v);
        wxA[r] = u - x0f;
        wyA[r] = v - y0f;
        // ex in [0, VDIM-2] so ex+1 is in range; far-OOB clamps land on zero texels
        int ex = min(max(__float2int_rz(x0f) + 2, 0), VDIM-2);
        int ey = min(max(__float2int_rz(y0f) + 2, 0), VDIM-1);
        idxA[r] = m ? (ey*VDIM + ex) : 0;   // masked: zero entry broadcast
    }

    // Phase 2: 8 LDG.64 back-to-back (pairs adjacent -> ~1 line per sample)
    uint2 TL[NREF], TR[NREF];
    #pragma unroll
    for (int r=0; r<NREF; r++) {
        const uint2* fm = g_v + (size_t)(b*NREF + r)*IMGV;
        TL[r] = __ldg(fm + idxA[r]);       // { t(y0,x0),   t(y0+1,x0)   }
        TR[r] = __ldg(fm + idxA[r] + 1);   // { t(y0,x0+1), t(y0+1,x0+1) }
    }

    // Phase 3: decode + accumulate
    float a0=0.f, a1=0.f, a2=0.f;
    #pragma unroll
    for (int r=0; r<NREF; r++) {
        float wx = wxA[r], wy = wyA[r];
        float wxl = 1.f - wx, wyt = 1.f - wy;
        float w00 = wxl*wyt, w01 = wx*wyt;
        float w10 = wxl*wy,  w11 = wx*wy;   // sums to 1 -> bias = NREF
        dec_acc(TL[r].x, w00, a0, a1, a2);
        dec_acc(TL[r].y, w10, a0, a1, a2);
        dec_acc(TR[r].x, w01, a0, a1, a2);
        dec_acc(TR[r].y, w11, a0, a1, a2);
    }

    // acc = NREF + sum(w * field * 2^-k)  ->  out = (acc - 4) * scale
    const float sRG = 0.25f * 2048.f / 2047.f;
    const float sB  = 0.25f * 1024.f / 1023.f;
    const float bRG = -4.f * sRG;
    const float bB  = -4.f * sB;

    float o0, o1, o2;
    if (m) {
        o0 = fmaf(a0, sRG, bRG);
        o1 = fmaf(a1, sRG, bRG);
        o2 = fmaf(a2, sB,  bB );
    } else {
        o0 = background[obase];
        o1 = background[obase + NPIX];
        o2 = background[obase + 2*NPIX];
    }

    out[obase]          = o0;
    out[obase + NPIX]   = o1;
    out[obase + 2*NPIX] = o2;
}

extern "C" void kernel_launch(void* const* d_in, const int* in_sizes, int n_in,
                              void* d_out, int out_size) {
    // metadata order: depth, cam_K, cam_W, image_ref, background,
    //                 cube_diagonal, cam_K_ref, cam_W_ref
    const float* depth      = (const float*)d_in[0];
    const float* cam_K      = (const float*)d_in[1];
    const float* cam_W      = (const float*)d_in[2];
    const float* image_ref  = (const float*)d_in[3];
    const float* background = (const float*)d_in[4];
    // d_in[5] = cube_diagonal: algebraically cancels -> unused
    const float* cam_K_ref  = (const float*)d_in[6];
    const float* cam_W_ref  = (const float*)d_in[7];
    float* out = (float*)d_out;

    int n_entries = BB*NREF*IMGV;              // 1,679,616 = 256 * 6561
    repack_kernel<<<n_entries/256, 256>>>(image_ref, cam_K, cam_W,
                                          cam_K_ref, cam_W_ref);

    dim3 block(32, 8, 1);
    dim3 grid(WW/32, HH/8, BB*NR);
    render_kernel<<<grid, block>>>(depth, background, out);
}